// round 1
// baseline (speedup 1.0000x reference)
#include <cuda_runtime.h>
#include <math.h>

#define NN 20000
#define NE 640000
#define NL 2
#define MAXR 2.5f
#define INV_NN 0.17677669529663687f   // 1/sqrt(32)

// ---------------- scratch (device globals; no allocs) ----------------
static __device__ float g_Q[64 * 2];
static __device__ float g_ys[2][NN * 64];
static __device__ float g_yv[2][NN * 192];
static __device__ float g_s1[NN * 64];
static __device__ float g_v1[NN * 192];
static __device__ float g_agg[NN * 256];          // (n, c, 4): vx,vy,vz,s
static __device__ float g_pos[NN * 3];
static __device__ float g_Bs[NL * 100 * 64 * 128];
static __device__ float g_Bv[NL * 100 * 64 * 64];

// ---------------- Q = polar factor of uplift_M (64x2) ----------------
__global__ void k_q(const float* __restrict__ M) {
    // single thread; double precision for safety
    double a = 0, b = 0, c = 0;
    for (int i = 0; i < 64; i++) {
        double m0 = M[2 * i], m1 = M[2 * i + 1];
        a += m0 * m0; b += m0 * m1; c += m1 * m1;
    }
    double det = a * c - b * b;
    double s = sqrt(det);
    double t = a + c;
    double denom = sqrt(t + 2.0 * s);
    // sqrt(S) = (S + s*I)/denom
    double p00 = (a + s) / denom, p01 = b / denom, p11 = (c + s) / denom;
    double pdet = p00 * p11 - p01 * p01;
    double i00 = p11 / pdet, i01 = -p01 / pdet, i11 = p00 / pdet;
    for (int i = 0; i < 64; i++) {
        double m0 = M[2 * i], m1 = M[2 * i + 1];
        g_Q[2 * i]     = (float)(m0 * i00 + m1 * i01);
        g_Q[2 * i + 1] = (float)(m0 * i01 + m1 * i11);
    }
}

// ------- Bs[l,a,c,o] = sum_e emb[a,e]*sc_s_w[l,c,e,o]; same for Bv -------
__global__ void k_bs(const float* __restrict__ emb,
                     const float* __restrict__ scs,
                     const float* __restrict__ scv) {
    const int TOTS = NL * 100 * 64 * 128;
    const int TOTV = NL * 100 * 64 * 64;
    for (int idx = blockIdx.x * blockDim.x + threadIdx.x; idx < TOTS + TOTV;
         idx += gridDim.x * blockDim.x) {
        if (idx < TOTS) {
            int o = idx & 127;
            int c = (idx >> 7) & 63;
            int a = (idx >> 13) % 100;
            int l = idx / (128 * 64 * 100);
            const float* w = scs + ((size_t)(l * 64 + c) * 32) * 128 + o;
            const float* em = emb + a * 32;
            float acc = 0.f;
#pragma unroll 8
            for (int e = 0; e < 32; e++) acc += em[e] * w[e * 128];
            g_Bs[idx] = acc;
        } else {
            int j = idx - TOTS;
            int o = j & 63;
            int c = (j >> 6) & 63;
            int a = (j >> 12) % 100;
            int l = j / (64 * 64 * 100);
            const float* w = scv + ((size_t)(l * 64 + c) * 32) * 64 + o;
            const float* em = emb + a * 32;
            float acc = 0.f;
#pragma unroll 8
            for (int e = 0; e < 32; e++) acc += em[e] * w[e * 64];
            g_Bv[j] = acc;
        }
    }
}

// ---------------- init: y_v = xv Q^T style uplift, y_s = 0 ----------------
__global__ void k_init(const float* __restrict__ x) {
    int i = blockIdx.x * blockDim.x + threadIdx.x;
    if (i >= NN * 64) return;
    int n = i >> 6, c = i & 63;
    float q0 = g_Q[c * 2], q1 = g_Q[c * 2 + 1];
    const float* xp = x + n * 6;
    float v0 = xp[0] * q0 + xp[3] * q1;
    float v1 = xp[1] * q0 + xp[4] * q1;
    float v2 = xp[2] * q0 + xp[5] * q1;
    int base = n * 192 + c * 3;
    g_yv[0][base + 0] = v0; g_yv[0][base + 1] = v1; g_yv[0][base + 2] = v2;
    g_yv[1][base + 0] = v0; g_yv[1][base + 1] = v1; g_yv[1][base + 2] = v2;
    g_ys[0][i] = 0.f; g_ys[1][i] = 0.f;
    if (c < 3) g_pos[n * 3 + c] = xp[c];
}

// ---------------- zero aggregation buffer ----------------
__global__ void k_zero() {
    float4 z = make_float4(0.f, 0.f, 0.f, 0.f);
    float4* p = reinterpret_cast<float4*>(g_agg);
    for (int i = blockIdx.x * blockDim.x + threadIdx.x; i < NN * 64;
         i += gridDim.x * blockDim.x)
        p[i] = z;
}

// ---------------- pre: s1 = y_s@lin1_s, v1 = y_v@lin1_v ----------------
__global__ void __launch_bounds__(256) k_pre(const float* __restrict__ lin1s,
                                             const float* __restrict__ lin1v,
                                             int layer, int cur) {
    __shared__ float sWs[4096], sWv[4096];
    __shared__ float sy[8][256];  // per node: ys[64] + yv[192]
    int tid = threadIdx.x;
    const float* Ws = lin1s + layer * 4096;
    const float* Wv = lin1v + layer * 4096;
    for (int k = tid; k < 4096; k += 256) { sWs[k] = Ws[k]; sWv[k] = Wv[k]; }
    const float* ys = g_ys[cur];
    const float* yv = g_yv[cur];
    int n0 = blockIdx.x * 8;
    for (int k = tid; k < 2048; k += 256) {
        int nn = k >> 8, j = k & 255;
        int n = n0 + nn;
        sy[nn][j] = (j < 64) ? ys[n * 64 + j] : yv[n * 192 + j - 64];
    }
    __syncthreads();
    for (int nn = 0; nn < 8; nn++) {
        int n = n0 + nn;
        if (tid < 64) {
            int d = tid;
            float acc = 0.f;
#pragma unroll 8
            for (int c = 0; c < 64; c++) acc += sy[nn][c] * sWs[c * 64 + d];
            g_s1[n * 64 + d] = acc;
        } else {
            int idx = tid - 64;
            int d = idx & 63, xx = idx >> 6;
            float acc = 0.f;
#pragma unroll 8
            for (int c = 0; c < 64; c++) acc += sy[nn][64 + c * 3 + xx] * sWv[c * 64 + d];
            g_v1[n * 192 + d * 3 + xx] = acc;
        }
    }
}

// ---------------- edge kernel: one warp per edge ----------------
__global__ void __launch_bounds__(256) k_edge(const int* __restrict__ esrc,
                                              const int* __restrict__ edst,
                                              const float* __restrict__ rW1,
                                              const float* __restrict__ rb1,
                                              const float* __restrict__ rW2,
                                              int layer) {
    __shared__ float sW1[256];
    __shared__ float sb1[32];
    __shared__ float sW2[4096];
    int tid = threadIdx.x;
    for (int k = tid; k < 256; k += 256) sW1[k] = rW1[layer * 256 + k];
    if (tid < 32) sb1[tid] = rb1[layer * 32 + tid];
    for (int k = tid; k < 4096; k += 256) sW2[k] = rW2[layer * 4096 + k];
    __syncthreads();
    int lane = tid & 31;
    int gwarp = (blockIdx.x * 256 + tid) >> 5;
    int nw = gridDim.x * 8;
    const float PI = 3.14159265358979f;
    for (int e = gwarp; e < NE; e += nw) {
        int src = esrc[e], dst = edst[e];
        float ev0 = g_pos[src * 3 + 0] - g_pos[dst * 3 + 0];
        float ev1 = g_pos[src * 3 + 1] - g_pos[dst * 3 + 1];
        float ev2 = g_pos[src * 3 + 2] - g_pos[dst * 3 + 2];
        float elen = sqrtf(ev0 * ev0 + ev1 * ev1 + ev2 * ev2);
        if (elen >= MAXR) continue;  // cutoff == 0 -> no contribution
        float safe = fmaxf(elen, 1e-9f);
        float inv = 1.0f / safe;
        float u = 2.f * (elen * (1.0f / MAXR) - 1.f);
        float cut = 0.5f * (1.f - __cosf(PI * u));
        float ca = cut * 1.7320508075688772f * inv;  // sqrt(3)*cut/safe
        float ea0 = ca * ev0, ea1 = ca * ev1, ea2 = ca * ev2;
        // radial basis via sin recurrence
        float th = (PI / MAXR) * safe;
        float sk = __sinf(th), c2 = 2.f * __cosf(th), skm1 = 0.f;
        float fac = 2.5298221281347035f * inv;  // sqrt(2/R)*sqrt(NB)/safe
        float hs = sb1[lane];
#pragma unroll
        for (int k = 0; k < 8; k++) {
            hs += (fac * sk) * sW1[k * 32 + lane];
            float t = c2 * sk - skm1; skm1 = sk; sk = t;
        }
        float hval = hs / (1.f + __expf(-hs));  // silu
        float w0 = 0.f, w1 = 0.f, w2 = 0.f, w3 = 0.f;
#pragma unroll
        for (int k = 0; k < 32; k++) {
            float hk = __shfl_sync(0xffffffffu, hval, k);
            const float* p = sW2 + k * 128 + lane;
            w0 += hk * p[0];  w1 += hk * p[32];
            w2 += hk * p[64]; w3 += hk * p[96];
        }
        const float* s1p = g_s1 + (size_t)src * 64;
        const float* v1p = g_v1 + (size_t)src * 192;
        float sa = s1p[lane] * w0;
        float sb = s1p[lane + 32] * w1;
        float da = w2 * (v1p[lane * 3] * ea0 + v1p[lane * 3 + 1] * ea1 + v1p[lane * 3 + 2] * ea2);
        float db = w3 * (v1p[(lane + 32) * 3] * ea0 + v1p[(lane + 32) * 3 + 1] * ea1 +
                         v1p[(lane + 32) * 3 + 2] * ea2);
        float4* ap = reinterpret_cast<float4*>(g_agg + (size_t)dst * 256);
        atomicAdd(ap + lane,      make_float4(sa * ea0, sa * ea1, sa * ea2, da));
        atomicAdd(ap + lane + 32, make_float4(sb * ea0, sb * ea1, sb * ea2, db));
    }
}

// ---------------- post: out_s/out_v, gates, state update, projection ----------------
__global__ void __launch_bounds__(128) k_post(const float* __restrict__ lin2s,
                                              const float* __restrict__ lin2v,
                                              const float* __restrict__ sis,
                                              const float* __restrict__ siv,
                                              const int* __restrict__ attr,
                                              const float* __restrict__ hv,
                                              const float* __restrict__ mv,
                                              int layer, int cur,
                                              float* __restrict__ outp) {
    extern __shared__ float sw[];
    float* sL2s = sw;            // 8192
    float* sL2v = sw + 8192;     // 4096
    float* sSs  = sw + 12288;    // 4096
    float* sSv  = sw + 16384;    // 4096
    __shared__ float s_Q[128];
    __shared__ float s_ys[64], s_aggs[64];
    __shared__ float s_yv[192], s_aggv[192];
    __shared__ float s_outs[128], s_outv[192];
    __shared__ float s_y2s[64], s_y2v[192];
    __shared__ float s_newv[192];
    int tid = threadIdx.x;
    const float* L2s = lin2s + layer * 8192;
    const float* L2v = lin2v + layer * 4096;
    const float* Ss = sis + layer * 4096;
    const float* Sv = siv + layer * 4096;
    for (int k = tid; k < 8192; k += 128) sL2s[k] = L2s[k];
    for (int k = tid; k < 4096; k += 128) { sL2v[k] = L2v[k]; sSs[k] = Ss[k]; sSv[k] = Sv[k]; }
    s_Q[tid] = g_Q[tid];
    float hh = hv[layer] * hv[layer];
    float m = mv[layer];
    float* ys_new = g_ys[cur ^ 1];
    float* yv_new = g_yv[cur ^ 1];
    const float* ys_cur = g_ys[cur];
    const float* yv_cur = g_yv[cur];
    __syncthreads();
    int n0 = blockIdx.x * 8;
    for (int nn = 0; nn < 8; nn++) {
        int n = n0 + nn;
        if (tid < 64) {
            s_ys[tid] = ys_cur[n * 64 + tid];
            s_aggs[tid] = g_agg[n * 256 + tid * 4 + 3] * INV_NN;
        }
        for (int j = tid; j < 192; j += 128) {
            int c = j / 3, xx = j - 3 * c;
            s_yv[j] = yv_cur[n * 192 + j];
            s_aggv[j] = g_agg[n * 256 + c * 4 + xx] * INV_NN;
        }
        __syncthreads();
        int a = attr[n];
        const float* Bs = g_Bs + (size_t)(layer * 100 + a) * 8192;
        const float* Bv = g_Bv + (size_t)(layer * 100 + a) * 4096;
        {
            float acc = 0.f;
#pragma unroll 8
            for (int c = 0; c < 64; c++)
                acc += s_aggs[c] * sL2s[c * 128 + tid] + s_ys[c] * Bs[c * 128 + tid];
            s_outs[tid] = acc;
        }
        if (tid < 64) {
            int d = tid;
            float a0 = 0.f, a1 = 0.f, a2 = 0.f;
#pragma unroll 8
            for (int c = 0; c < 64; c++) {
                float w = sL2v[c * 64 + d], bw = Bv[c * 64 + d];
                a0 += s_aggv[c * 3 + 0] * w + s_yv[c * 3 + 0] * bw;
                a1 += s_aggv[c * 3 + 1] * w + s_yv[c * 3 + 1] * bw;
                a2 += s_aggv[c * 3 + 2] * w + s_yv[c * 3 + 2] * bw;
            }
            s_outv[d * 3 + 0] = a0; s_outv[d * 3 + 1] = a1; s_outv[d * 3 + 2] = a2;
        } else {
            int d = tid - 64;
            float y2 = 0.f, b0 = 0.f, b1 = 0.f, b2 = 0.f;
#pragma unroll 8
            for (int c = 0; c < 64; c++) {
                float wsv = sSv[c * 64 + d];
                y2 += s_ys[c] * sSs[c * 64 + d];
                b0 += s_yv[c * 3 + 0] * wsv;
                b1 += s_yv[c * 3 + 1] * wsv;
                b2 += s_yv[c * 3 + 2] * wsv;
            }
            s_y2s[d] = y2;
            s_y2v[d * 3 + 0] = b0; s_y2v[d * 3 + 1] = b1; s_y2v[d * 3 + 2] = b2;
        }
        __syncthreads();
        if (tid < 64) {
            int c = tid;
            float os = s_outs[c];
            float gs = os / (1.f + __expf(-os));                // silu
            float gate = 1.f / (1.f + __expf(-s_outs[64 + c])); // sigmoid
            float yo = ys_new[n * 64 + c];                      // y_old
            float ns = 2.f * s_ys[c] - yo + hh * (m * gs + (m - 1.f) * s_y2s[c]);
            ys_new[n * 64 + c] = ns;
#pragma unroll
            for (int xx = 0; xx < 3; xx++) {
                float yov = yv_new[n * 192 + c * 3 + xx];
                float nv = 2.f * s_yv[c * 3 + xx] - yov +
                           hh * (m * gate * s_outv[c * 3 + xx] + (m - 1.f) * s_y2v[c * 3 + xx]);
                yv_new[n * 192 + c * 3 + xx] = nv;
                s_newv[c * 3 + xx] = nv;
            }
        }
        __syncthreads();
        if (tid < 6) {
            int k = tid / 3, xx = tid - 3 * k;
            float acc = 0.f;
#pragma unroll 8
            for (int c = 0; c < 64; c++) acc += s_newv[c * 3 + xx] * s_Q[c * 2 + k];
            if (layer == 0) {
                if (k == 0) g_pos[n * 3 + xx] = acc;
            } else {
                outp[n * 6 + k * 3 + xx] = acc;
            }
        }
        __syncthreads();
    }
}

// ---------------- launch ----------------
extern "C" void kernel_launch(void* const* d_in, const int* in_sizes, int n_in,
                              void* d_out, int out_size) {
    const float* x        = (const float*)d_in[0];
    const int*   attr     = (const int*)d_in[2];
    const int*   esrc     = (const int*)d_in[3];
    const int*   edst     = (const int*)d_in[4];
    const float* emb      = (const float*)d_in[5];
    const float* uplift   = (const float*)d_in[6];
    const float* h        = (const float*)d_in[7];
    const float* mix      = (const float*)d_in[8];
    const float* rW1      = (const float*)d_in[9];
    const float* rb1      = (const float*)d_in[10];
    const float* rW2      = (const float*)d_in[11];
    const float* lin1s    = (const float*)d_in[12];
    const float* lin1v    = (const float*)d_in[13];
    const float* lin2s    = (const float*)d_in[14];
    const float* lin2v    = (const float*)d_in[15];
    const float* scs      = (const float*)d_in[16];
    const float* scv      = (const float*)d_in[17];
    const float* sis      = (const float*)d_in[18];
    const float* siv      = (const float*)d_in[19];
    float* out = (float*)d_out;

    cudaFuncSetAttribute(k_post, cudaFuncAttributeMaxDynamicSharedMemorySize, 84 * 1024);

    k_q<<<1, 1>>>(uplift);
    k_bs<<<2400, 256>>>(emb, scs, scv);
    k_init<<<(NN * 64 + 255) / 256, 256>>>(x);
    int cur = 0;
    for (int l = 0; l < NL; l++) {
        k_zero<<<1024, 256>>>();
        k_pre<<<NN / 8, 256>>>(lin1s, lin1v, l, cur);
        k_edge<<<2048, 256>>>(esrc, edst, rW1, rb1, rW2, l);
        k_post<<<NN / 8, 128, 81920>>>(lin2s, lin2v, sis, siv, attr, h, mix, l, cur, out);
        cur ^= 1;
    }
}

// round 2
// speedup vs baseline: 1.0084x; 1.0084x over previous
#include <cuda_runtime.h>
#include <math.h>

#define NN 20000
#define NE 640000
#define NL 2
#define MAXR 2.5f
#define INV_NN 0.17677669529663687f   // 1/sqrt(32)

// ---------------- scratch (device globals; no allocs) ----------------
static __device__ float g_Q[64 * 2];
static __device__ float g_ys[2][NN * 64];
static __device__ float g_yv[2][NN * 192];
static __device__ float g_s1[NN * 64];
static __device__ float g_v1[NN * 192];          // [n][3][64] x-major
static __device__ float g_agg[NN * 256];         // (n, c, 4): vx,vy,vz,s
static __device__ float g_pos[NN * 3];
static __device__ float g_Bs[NL * 100 * 64 * 128];
static __device__ float g_Bv[NL * 100 * 64 * 64];
// edge CSR sort
static __device__ int g_ecnt[NN];
static __device__ int g_eoff[NN];
static __device__ int g_eppos[NN];
static __device__ int g_ssrc[NE];
static __device__ int g_sdst[NE];
// node sort by attr
static __device__ int g_ncnt[128];
static __device__ int g_noff[128];
static __device__ int g_nppos[128];
static __device__ int g_nidx[NN];

// ---------------- Q = polar factor of uplift_M (64x2) ----------------
__global__ void k_q(const float* __restrict__ M) {
    double a = 0, b = 0, c = 0;
    for (int i = 0; i < 64; i++) {
        double m0 = M[2 * i], m1 = M[2 * i + 1];
        a += m0 * m0; b += m0 * m1; c += m1 * m1;
    }
    double det = a * c - b * b;
    double s = sqrt(det);
    double t = a + c;
    double denom = sqrt(t + 2.0 * s);
    double p00 = (a + s) / denom, p01 = b / denom, p11 = (c + s) / denom;
    double pdet = p00 * p11 - p01 * p01;
    double i00 = p11 / pdet, i01 = -p01 / pdet, i11 = p00 / pdet;
    for (int i = 0; i < 64; i++) {
        double m0 = M[2 * i], m1 = M[2 * i + 1];
        g_Q[2 * i]     = (float)(m0 * i00 + m1 * i01);
        g_Q[2 * i + 1] = (float)(m0 * i01 + m1 * i11);
    }
}

// ------- Bs[l,a,c,o] = sum_e emb[a,e]*sc_s_w[l,c,e,o]; same for Bv -------
__global__ void k_bs(const float* __restrict__ emb,
                     const float* __restrict__ scs,
                     const float* __restrict__ scv) {
    const int TOTS = NL * 100 * 64 * 128;
    const int TOTV = NL * 100 * 64 * 64;
    for (int idx = blockIdx.x * blockDim.x + threadIdx.x; idx < TOTS + TOTV;
         idx += gridDim.x * blockDim.x) {
        if (idx < TOTS) {
            int o = idx & 127;
            int c = (idx >> 7) & 63;
            int a = (idx >> 13) % 100;
            int l = idx / (128 * 64 * 100);
            const float* w = scs + ((size_t)(l * 64 + c) * 32) * 128 + o;
            const float* em = emb + a * 32;
            float acc = 0.f;
#pragma unroll 8
            for (int e = 0; e < 32; e++) acc += em[e] * w[e * 128];
            g_Bs[idx] = acc;
        } else {
            int j = idx - TOTS;
            int o = j & 63;
            int c = (j >> 6) & 63;
            int a = (j >> 12) % 100;
            int l = j / (64 * 64 * 100);
            const float* w = scv + ((size_t)(l * 64 + c) * 32) * 64 + o;
            const float* em = emb + a * 32;
            float acc = 0.f;
#pragma unroll 8
            for (int e = 0; e < 32; e++) acc += em[e] * w[e * 64];
            g_Bv[j] = acc;
        }
    }
}

// ---------------- init ----------------
__global__ void k_init(const float* __restrict__ x) {
    int i = blockIdx.x * blockDim.x + threadIdx.x;
    if (i >= NN * 64) return;
    int n = i >> 6, c = i & 63;
    float q0 = g_Q[c * 2], q1 = g_Q[c * 2 + 1];
    const float* xp = x + n * 6;
    float v0 = xp[0] * q0 + xp[3] * q1;
    float v1 = xp[1] * q0 + xp[4] * q1;
    float v2 = xp[2] * q0 + xp[5] * q1;
    int base = n * 192 + c * 3;
    g_yv[0][base + 0] = v0; g_yv[0][base + 1] = v1; g_yv[0][base + 2] = v2;
    g_yv[1][base + 0] = v0; g_yv[1][base + 1] = v1; g_yv[1][base + 2] = v2;
    g_ys[0][i] = 0.f; g_ys[1][i] = 0.f;
    if (c < 3) g_pos[n * 3 + c] = xp[c];
}

// ---------------- sorting infrastructure ----------------
__global__ void k_zero_cnt() {
    int i = blockIdx.x * blockDim.x + threadIdx.x;
    if (i < NN) { g_ecnt[i] = 0; g_eppos[i] = 0; }
    if (i < 128) { g_ncnt[i] = 0; g_nppos[i] = 0; }
}
__global__ void k_hist_e(const int* __restrict__ edst) {
    for (int e = blockIdx.x * blockDim.x + threadIdx.x; e < NE;
         e += gridDim.x * blockDim.x)
        atomicAdd(&g_ecnt[edst[e]], 1);
}
__global__ void k_hist_n(const int* __restrict__ attr) {
    for (int n = blockIdx.x * blockDim.x + threadIdx.x; n < NN;
         n += gridDim.x * blockDim.x)
        atomicAdd(&g_ncnt[attr[n]], 1);
}
__global__ void __launch_bounds__(512) k_scan_e() {
    __shared__ int sp[512];
    int t = threadIdx.x;
    const int CH = 40;  // 512*40 >= 20000
    int base = t * CH;
    int part = 0;
    for (int i = 0; i < CH; i++) {
        int idx = base + i;
        if (idx < NN) part += g_ecnt[idx];
    }
    sp[t] = part;
    __syncthreads();
    for (int off = 1; off < 512; off <<= 1) {
        int v = (t >= off) ? sp[t - off] : 0;
        __syncthreads();
        sp[t] += v;
        __syncthreads();
    }
    int run = sp[t] - part;
    for (int i = 0; i < CH; i++) {
        int idx = base + i;
        if (idx < NN) { g_eoff[idx] = run; run += g_ecnt[idx]; }
    }
}
__global__ void __launch_bounds__(128) k_scan_n() {
    __shared__ int sp[128];
    int t = threadIdx.x;
    int part = (t < 100) ? g_ncnt[t] : 0;
    sp[t] = part;
    __syncthreads();
    for (int off = 1; off < 128; off <<= 1) {
        int v = (t >= off) ? sp[t - off] : 0;
        __syncthreads();
        sp[t] += v;
        __syncthreads();
    }
    if (t < 100) g_noff[t] = sp[t] - part;
}
__global__ void k_scat_e(const int* __restrict__ esrc, const int* __restrict__ edst) {
    for (int e = blockIdx.x * blockDim.x + threadIdx.x; e < NE;
         e += gridDim.x * blockDim.x) {
        int d = edst[e];
        int p = g_eoff[d] + atomicAdd(&g_eppos[d], 1);
        g_ssrc[p] = esrc[e];
        g_sdst[p] = d;
    }
}
__global__ void k_scat_n(const int* __restrict__ attr) {
    for (int n = blockIdx.x * blockDim.x + threadIdx.x; n < NN;
         n += gridDim.x * blockDim.x) {
        int a = attr[n];
        int p = g_noff[a] + atomicAdd(&g_nppos[a], 1);
        g_nidx[p] = n;
    }
}

// ---------------- zero aggregation buffer ----------------
__global__ void k_zero() {
    float4 z = make_float4(0.f, 0.f, 0.f, 0.f);
    float4* p = reinterpret_cast<float4*>(g_agg);
    for (int i = blockIdx.x * blockDim.x + threadIdx.x; i < NN * 64;
         i += gridDim.x * blockDim.x)
        p[i] = z;
}

// ---------------- pre: s1 = y_s@lin1_s, v1 = y_v@lin1_v (v1 x-major) --------
__global__ void __launch_bounds__(256) k_pre(const float* __restrict__ lin1s,
                                             const float* __restrict__ lin1v,
                                             int layer, int cur) {
    __shared__ float sWs[4096], sWv[4096];
    __shared__ float sy[8][256];
    int tid = threadIdx.x;
    const float* Ws = lin1s + layer * 4096;
    const float* Wv = lin1v + layer * 4096;
    for (int k = tid; k < 4096; k += 256) { sWs[k] = Ws[k]; sWv[k] = Wv[k]; }
    const float* ys = g_ys[cur];
    const float* yv = g_yv[cur];
    int n0 = blockIdx.x * 8;
    for (int k = tid; k < 2048; k += 256) {
        int nn = k >> 8, j = k & 255;
        int n = n0 + nn;
        sy[nn][j] = (j < 64) ? ys[n * 64 + j] : yv[n * 192 + j - 64];
    }
    __syncthreads();
    for (int nn = 0; nn < 8; nn++) {
        int n = n0 + nn;
        if (tid < 64) {
            int d = tid;
            float acc = 0.f;
#pragma unroll 8
            for (int c = 0; c < 64; c++) acc += sy[nn][c] * sWs[c * 64 + d];
            g_s1[n * 64 + d] = acc;
        } else {
            int idx = tid - 64;
            int d = idx & 63, xx = idx >> 6;
            float acc = 0.f;
#pragma unroll 8
            for (int c = 0; c < 64; c++) acc += sy[nn][64 + c * 3 + xx] * sWv[c * 64 + d];
            g_v1[n * 192 + xx * 64 + d] = acc;   // x-major
        }
    }
}

// ---------------- edge kernel: warp per edge over dst-sorted edges ----------
__global__ void __launch_bounds__(256) k_edge(const float* __restrict__ rW1,
                                              const float* __restrict__ rb1,
                                              const float* __restrict__ rW2,
                                              int layer) {
    __shared__ float sW1[256];
    __shared__ float sb1v[32];
    __shared__ float sW2t[4096];   // [k][lane][4] interleaved
    int tid = threadIdx.x;
    for (int k = tid; k < 256; k += 256) sW1[k] = rW1[layer * 256 + k];
    if (tid < 32) sb1v[tid] = rb1[layer * 32 + tid];
    for (int t = tid; t < 4096; t += 256) {
        int k = t >> 7, r = t & 127, ln = r >> 2, g = r & 3;
        sW2t[t] = rW2[layer * 4096 + k * 128 + g * 32 + ln];
    }
    __syncthreads();
    int lane = tid & 31;
    int warp = (blockIdx.x * 256 + tid) >> 5;
    const int K = 40;
    int e0 = warp * K;
    if (e0 >= NE) return;
    int e1 = e0 + K; if (e1 > NE) e1 = NE;
    float4 acc0 = make_float4(0.f, 0.f, 0.f, 0.f);
    float4 acc1 = make_float4(0.f, 0.f, 0.f, 0.f);
    bool touched = false;
    int cur = -1;
    float dp0 = 0.f, dp1 = 0.f, dp2 = 0.f;
    const float PI = 3.14159265358979f;
    for (int e = e0; e < e1; e++) {
        int dst = g_sdst[e];
        if (dst != cur) {
            if (touched) {
                float4* ap = reinterpret_cast<float4*>(g_agg + (size_t)cur * 256);
                atomicAdd(ap + lane, acc0);
                atomicAdd(ap + lane + 32, acc1);
                acc0 = make_float4(0.f, 0.f, 0.f, 0.f);
                acc1 = make_float4(0.f, 0.f, 0.f, 0.f);
                touched = false;
            }
            cur = dst;
            dp0 = g_pos[dst * 3 + 0];
            dp1 = g_pos[dst * 3 + 1];
            dp2 = g_pos[dst * 3 + 2];
        }
        int src = g_ssrc[e];
        float ev0 = g_pos[src * 3 + 0] - dp0;
        float ev1 = g_pos[src * 3 + 1] - dp1;
        float ev2 = g_pos[src * 3 + 2] - dp2;
        float l2 = ev0 * ev0 + ev1 * ev1 + ev2 * ev2;
        if (l2 >= MAXR * MAXR) continue;
        float elen = sqrtf(l2);
        float safe = fmaxf(elen, 1e-9f);
        float inv = 1.0f / safe;
        float u = 2.f * (elen * (1.0f / MAXR) - 1.f);
        float cut = 0.5f * (1.f - __cosf(PI * u));
        float ca = cut * 1.7320508075688772f * inv;
        float ea0 = ca * ev0, ea1 = ca * ev1, ea2 = ca * ev2;
        // radial basis via sin recurrence
        float th = (PI / MAXR) * safe;
        float sk = __sinf(th), c2 = 2.f * __cosf(th), skm1 = 0.f;
        float fac = 2.5298221281347035f * inv;
        float hs = sb1v[lane];
#pragma unroll
        for (int k = 0; k < 8; k++) {
            hs += (fac * sk) * sW1[k * 32 + lane];
            float t = c2 * sk - skm1; skm1 = sk; sk = t;
        }
        float hval = hs / (1.f + __expf(-hs));  // silu
        float w0 = 0.f, w1 = 0.f, w2 = 0.f, w3 = 0.f;
#pragma unroll
        for (int k = 0; k < 32; k++) {
            float hk = __shfl_sync(0xffffffffu, hval, k);
            float4 wv = *reinterpret_cast<const float4*>(&sW2t[k * 128 + lane * 4]);
            w0 = fmaf(hk, wv.x, w0);
            w1 = fmaf(hk, wv.y, w1);
            w2 = fmaf(hk, wv.z, w2);
            w3 = fmaf(hk, wv.w, w3);
        }
        const float* s1p = g_s1 + (size_t)src * 64;
        const float* v1p = g_v1 + (size_t)src * 192;  // [3][64]
        float sa = s1p[lane] * w0;
        float sb = s1p[lane + 32] * w1;
        float da = w2 * (v1p[lane] * ea0 + v1p[64 + lane] * ea1 + v1p[128 + lane] * ea2);
        float db = w3 * (v1p[lane + 32] * ea0 + v1p[96 + lane] * ea1 + v1p[160 + lane] * ea2);
        acc0.x += sa * ea0; acc0.y += sa * ea1; acc0.z += sa * ea2; acc0.w += da;
        acc1.x += sb * ea0; acc1.y += sb * ea1; acc1.z += sb * ea2; acc1.w += db;
        touched = true;
    }
    if (touched) {
        float4* ap = reinterpret_cast<float4*>(g_agg + (size_t)cur * 256);
        atomicAdd(ap + lane, acc0);
        atomicAdd(ap + lane + 32, acc1);
    }
}

// ---------------- post ----------------
__global__ void __launch_bounds__(128) k_post(const float* __restrict__ lin2s,
                                              const float* __restrict__ lin2v,
                                              const float* __restrict__ sis,
                                              const float* __restrict__ siv,
                                              const int* __restrict__ attr,
                                              const float* __restrict__ hv,
                                              const float* __restrict__ mv,
                                              int layer, int cur,
                                              float* __restrict__ outp) {
    extern __shared__ float sw[];
    float* sL2s = sw;            // 8192
    float* sL2v = sw + 8192;     // 4096
    float* sSs  = sw + 12288;    // 4096
    float* sSv  = sw + 16384;    // 4096
    __shared__ float s_Q[128];
    __shared__ float s_ys[64], s_aggs[64];
    __shared__ float s_yv[192], s_aggv[192];
    __shared__ float s_outs[128], s_outv[192];
    __shared__ float s_y2s[64], s_y2v[192];
    __shared__ float s_newv[192];
    int tid = threadIdx.x;
    const float* L2s = lin2s + layer * 8192;
    const float* L2v = lin2v + layer * 4096;
    const float* Ss = sis + layer * 4096;
    const float* Sv = siv + layer * 4096;
    for (int k = tid; k < 8192; k += 128) sL2s[k] = L2s[k];
    for (int k = tid; k < 4096; k += 128) { sL2v[k] = L2v[k]; sSs[k] = Ss[k]; sSv[k] = Sv[k]; }
    s_Q[tid] = g_Q[tid];
    float hh = hv[layer] * hv[layer];
    float m = mv[layer];
    float* ys_new = g_ys[cur ^ 1];
    float* yv_new = g_yv[cur ^ 1];
    const float* ys_cur = g_ys[cur];
    const float* yv_cur = g_yv[cur];
    __syncthreads();
    int p0 = blockIdx.x * 8;
    for (int nn = 0; nn < 8; nn++) {
        int n = g_nidx[p0 + nn];   // attr-sorted order
        if (tid < 64) {
            s_ys[tid] = ys_cur[n * 64 + tid];
            s_aggs[tid] = g_agg[n * 256 + tid * 4 + 3] * INV_NN;
        }
        for (int j = tid; j < 192; j += 128) {
            int c = j / 3, xx = j - 3 * c;
            s_yv[j] = yv_cur[n * 192 + j];
            s_aggv[j] = g_agg[n * 256 + c * 4 + xx] * INV_NN;
        }
        __syncthreads();
        int a = attr[n];
        const float* Bs = g_Bs + (size_t)(layer * 100 + a) * 8192;
        const float* Bv = g_Bv + (size_t)(layer * 100 + a) * 4096;
        {
            float acc = 0.f;
#pragma unroll 8
            for (int c = 0; c < 64; c++)
                acc += s_aggs[c] * sL2s[c * 128 + tid] + s_ys[c] * Bs[c * 128 + tid];
            s_outs[tid] = acc;
        }
        if (tid < 64) {
            int d = tid;
            float a0 = 0.f, a1 = 0.f, a2 = 0.f;
#pragma unroll 8
            for (int c = 0; c < 64; c++) {
                float w = sL2v[c * 64 + d], bw = Bv[c * 64 + d];
                a0 += s_aggv[c * 3 + 0] * w + s_yv[c * 3 + 0] * bw;
                a1 += s_aggv[c * 3 + 1] * w + s_yv[c * 3 + 1] * bw;
                a2 += s_aggv[c * 3 + 2] * w + s_yv[c * 3 + 2] * bw;
            }
            s_outv[d * 3 + 0] = a0; s_outv[d * 3 + 1] = a1; s_outv[d * 3 + 2] = a2;
        } else {
            int d = tid - 64;
            float y2 = 0.f, b0 = 0.f, b1 = 0.f, b2 = 0.f;
#pragma unroll 8
            for (int c = 0; c < 64; c++) {
                float wsv = sSv[c * 64 + d];
                y2 += s_ys[c] * sSs[c * 64 + d];
                b0 += s_yv[c * 3 + 0] * wsv;
                b1 += s_yv[c * 3 + 1] * wsv;
                b2 += s_yv[c * 3 + 2] * wsv;
            }
            s_y2s[d] = y2;
            s_y2v[d * 3 + 0] = b0; s_y2v[d * 3 + 1] = b1; s_y2v[d * 3 + 2] = b2;
        }
        __syncthreads();
        if (tid < 64) {
            int c = tid;
            float os = s_outs[c];
            float gs = os / (1.f + __expf(-os));
            float gate = 1.f / (1.f + __expf(-s_outs[64 + c]));
            float yo = ys_new[n * 64 + c];
            float ns = 2.f * s_ys[c] - yo + hh * (m * gs + (m - 1.f) * s_y2s[c]);
            ys_new[n * 64 + c] = ns;
#pragma unroll
            for (int xx = 0; xx < 3; xx++) {
                float yov = yv_new[n * 192 + c * 3 + xx];
                float nv = 2.f * s_yv[c * 3 + xx] - yov +
                           hh * (m * gate * s_outv[c * 3 + xx] + (m - 1.f) * s_y2v[c * 3 + xx]);
                yv_new[n * 192 + c * 3 + xx] = nv;
                s_newv[c * 3 + xx] = nv;
            }
        }
        __syncthreads();
        if (tid < 6) {
            int k = tid / 3, xx = tid - 3 * k;
            float acc = 0.f;
#pragma unroll 8
            for (int c = 0; c < 64; c++) acc += s_newv[c * 3 + xx] * s_Q[c * 2 + k];
            if (layer == 0) {
                if (k == 0) g_pos[n * 3 + xx] = acc;
            } else {
                outp[n * 6 + k * 3 + xx] = acc;
            }
        }
        __syncthreads();
    }
}

// ---------------- launch ----------------
extern "C" void kernel_launch(void* const* d_in, const int* in_sizes, int n_in,
                              void* d_out, int out_size) {
    const float* x        = (const float*)d_in[0];
    const int*   attr     = (const int*)d_in[2];
    const int*   esrc     = (const int*)d_in[3];
    const int*   edst     = (const int*)d_in[4];
    const float* emb      = (const float*)d_in[5];
    const float* uplift   = (const float*)d_in[6];
    const float* h        = (const float*)d_in[7];
    const float* mix      = (const float*)d_in[8];
    const float* rW1      = (const float*)d_in[9];
    const float* rb1      = (const float*)d_in[10];
    const float* rW2      = (const float*)d_in[11];
    const float* lin1s    = (const float*)d_in[12];
    const float* lin1v    = (const float*)d_in[13];
    const float* lin2s    = (const float*)d_in[14];
    const float* lin2v    = (const float*)d_in[15];
    const float* scs      = (const float*)d_in[16];
    const float* scv      = (const float*)d_in[17];
    const float* sis      = (const float*)d_in[18];
    const float* siv      = (const float*)d_in[19];
    float* out = (float*)d_out;

    cudaFuncSetAttribute(k_post, cudaFuncAttributeMaxDynamicSharedMemorySize, 84 * 1024);

    k_q<<<1, 1>>>(uplift);
    k_bs<<<2400, 256>>>(emb, scs, scv);
    k_init<<<(NN * 64 + 255) / 256, 256>>>(x);
    // build dst-sorted edge list + attr-sorted node list (once per call)
    k_zero_cnt<<<(NN + 255) / 256, 256>>>();
    k_hist_e<<<1280, 256>>>(edst);
    k_hist_n<<<80, 256>>>(attr);
    k_scan_e<<<1, 512>>>();
    k_scan_n<<<1, 128>>>();
    k_scat_e<<<1280, 256>>>(esrc, edst);
    k_scat_n<<<80, 256>>>(attr);
    int cur = 0;
    for (int l = 0; l < NL; l++) {
        k_zero<<<1024, 256>>>();
        k_pre<<<NN / 8, 256>>>(lin1s, lin1v, l, cur);
        k_edge<<<2048, 256>>>(rW1, rb1, rW2, l);
        k_post<<<NN / 8, 128, 81920>>>(lin2s, lin2v, sis, siv, attr, h, mix, l, cur, out);
        cur ^= 1;
    }
}